// round 14
// baseline (speedup 1.0000x reference)
#include <cuda_runtime.h>
#include <cuda_bf16.h>
#include <cstdint>

#define N_NODES 100000
#define CIN 128
#define CHID 128
#define COUT 64
#define MAXE 1600000
#define SCAN_BLOCKS ((N_NODES + 255) / 256)

// ---------------- scratch ----------------
__device__ __align__(16) float g_mean1[(size_t)N_NODES * CIN];
__device__ __align__(16) float g_p    [(size_t)N_NODES * CHID];   // x @ W1r + b1
__device__ __align__(16) float g_h    [(size_t)N_NODES * CHID];
__device__ __align__(16) float g_t    [(size_t)N_NODES * COUT];
__device__ __align__(16) float g_r    [(size_t)N_NODES * COUT];
__device__ int g_degi  [N_NODES];
__device__ int g_row   [N_NODES + 1];
__device__ int g_cursor[N_NODES];
__device__ int g_srcbuf[MAXE];
__device__ int g_dstbuf[MAXE];
__device__ int g_csr   [MAXE];
__device__ int g_bsum  [512];
__device__ int g_is64;
// pre-split weights, transposed [n][kpair] u32 (bf16x2)
__device__ __align__(16) uint32_t g_w1hi[128 * 128];
__device__ __align__(16) uint32_t g_w1lo[128 * 128];
__device__ __align__(16) uint32_t g_w2hi[128 * 64];
__device__ __align__(16) uint32_t g_w2lo[128 * 64];

// ---------------- bf16 split helpers ----------------
__device__ __forceinline__ void bf16_split2(float f0, float f1,
                                            uint32_t& hi, uint32_t& lo) {
    __nv_bfloat16 h0 = __float2bfloat16(f0);
    __nv_bfloat16 h1 = __float2bfloat16(f1);
    float r0 = f0 - __bfloat162float(h0);
    float r1 = f1 - __bfloat162float(h1);
    __nv_bfloat16 l0 = __float2bfloat16(r0);
    __nv_bfloat16 l1 = __float2bfloat16(r1);
    hi = ((uint32_t)__bfloat16_as_ushort(h1) << 16) | __bfloat16_as_ushort(h0);
    lo = ((uint32_t)__bfloat16_as_ushort(l1) << 16) | __bfloat16_as_ushort(l0);
}

__device__ __forceinline__ void mma_bf16(float* d, const uint32_t* a,
                                         const uint32_t* b) {
    asm volatile(
        "mma.sync.aligned.m16n8k16.row.col.f32.bf16.bf16.f32 "
        "{%0,%1,%2,%3}, {%4,%5,%6,%7}, {%8,%9}, {%0,%1,%2,%3};"
        : "+f"(d[0]), "+f"(d[1]), "+f"(d[2]), "+f"(d[3])
        : "r"(a[0]), "r"(a[1]), "r"(a[2]), "r"(a[3]), "r"(b[0]), "r"(b[1]));
}

// ---------------- prep: pre-split W1/W2 into bf16 hi/lo, transposed ----------------
__global__ void prep_w1(const float* __restrict__ W1l,
                        const float* __restrict__ W1r) {
    int idx = blockIdx.x * blockDim.x + threadIdx.x;   // 16384
    if (idx >= 128 * 128) return;
    int n = idx >> 7, kp = idx & 127;
    int k0 = 2 * kp;
    float a = (k0 < 128) ? W1l[(size_t)k0 * 128 + n] : W1r[(size_t)(k0 - 128) * 128 + n];
    float c = (k0 + 1 < 128) ? W1l[(size_t)(k0 + 1) * 128 + n]
                             : W1r[(size_t)(k0 + 1 - 128) * 128 + n];
    uint32_t hi, lo;
    bf16_split2(a, c, hi, lo);
    g_w1hi[idx] = hi;
    g_w1lo[idx] = lo;
}

__global__ void prep_w2(const float* __restrict__ W2l,
                        const float* __restrict__ W2r) {
    int idx = blockIdx.x * blockDim.x + threadIdx.x;   // 8192
    if (idx >= 128 * 64) return;
    int n = idx >> 6, kp = idx & 63;
    int k0 = 2 * kp;
    const float* wb = (n < 64) ? (W2l + n) : (W2r + (n - 64));
    float a = wb[(size_t)k0 * 64];
    float c = wb[(size_t)(k0 + 1) * 64];
    uint32_t hi, lo;
    bf16_split2(a, c, hi, lo);
    g_w2hi[idx] = hi;
    g_w2lo[idx] = lo;
}

// ---------------- zero deg + init flag ----------------
__global__ void zero_deg() {
    int i = blockIdx.x * blockDim.x + threadIdx.x;
    if (i < N_NODES) g_degi[i] = 0;
    if (i == 0) g_is64 = 1;
}

// ---------------- detect edge_index dtype ----------------
__global__ void detect_kernel(const long long* __restrict__ ei, long long n) {
    long long i = (long long)blockIdx.x * blockDim.x + threadIdx.x;
    long long stride = (long long)gridDim.x * blockDim.x;
    for (; i < n; i += stride) {
        unsigned long long v = (unsigned long long)ei[i];
        if (v >= (unsigned long long)N_NODES) { g_is64 = 0; return; }
    }
}

// ---------------- decode edges + degree histogram ----------------
__global__ void decode_count(const void* __restrict__ ei_raw, int E) {
    int e = blockIdx.x * blockDim.x + threadIdx.x;
    if (e >= E) return;
    int src, dst;
    if (g_is64) {
        const long long* ei = (const long long*)ei_raw;
        src = (int)ei[e]; dst = (int)ei[(size_t)E + e];
    } else {
        const int* ei = (const int*)ei_raw;
        src = ei[e]; dst = ei[(size_t)E + e];
    }
    if ((unsigned)src >= N_NODES) src = 0;
    if ((unsigned)dst >= N_NODES) dst = 0;
    g_srcbuf[e] = src;
    g_dstbuf[e] = dst;
    atomicAdd(&g_degi[dst], 1);
}

// ---------------- scan phases ----------------
__global__ void block_sum_kernel() {
    int i = blockIdx.x * 256 + threadIdx.x;
    int v = (i < N_NODES) ? g_degi[i] : 0;
#pragma unroll
    for (int o = 16; o; o >>= 1) v += __shfl_down_sync(0xffffffffu, v, o);
    __shared__ int ws[8];
    if ((threadIdx.x & 31) == 0) ws[threadIdx.x >> 5] = v;
    __syncthreads();
    if (threadIdx.x < 8) {
        int s = ws[threadIdx.x];
#pragma unroll
        for (int o = 4; o; o >>= 1) s += __shfl_down_sync(0xffu, s, o);
        if (threadIdx.x == 0) g_bsum[blockIdx.x] = s;
    }
}

__global__ void scan_bsum_kernel() {
    __shared__ int sp[512];
    int tid = threadIdx.x;
    int v = (tid < SCAN_BLOCKS) ? g_bsum[tid] : 0;
    sp[tid] = v;
    __syncthreads();
    for (int off = 1; off < 512; off <<= 1) {
        int t = (tid >= off) ? sp[tid - off] : 0;
        __syncthreads();
        sp[tid] += t;
        __syncthreads();
    }
    if (tid < SCAN_BLOCKS) g_bsum[tid] = sp[tid] - v;
    if (tid == SCAN_BLOCKS - 1) g_row[N_NODES] = sp[tid];
}

__global__ void block_scan_kernel() {
    int i = blockIdx.x * 256 + threadIdx.x;
    int lane = threadIdx.x & 31, warp = threadIdx.x >> 5;
    int v = (i < N_NODES) ? g_degi[i] : 0;
    int s = v;
#pragma unroll
    for (int o = 1; o < 32; o <<= 1) {
        int t = __shfl_up_sync(0xffffffffu, s, o);
        if (lane >= o) s += t;
    }
    __shared__ int ws[8];
    if (lane == 31) ws[warp] = s;
    __syncthreads();
    if (threadIdx.x == 0) {
        int run = 0;
#pragma unroll
        for (int w = 0; w < 8; w++) { int t = ws[w]; ws[w] = run; run += t; }
    }
    __syncthreads();
    int excl = (s - v) + ws[warp] + g_bsum[blockIdx.x];
    if (i < N_NODES) { g_row[i] = excl; g_cursor[i] = excl; }
}

__global__ void scatter_kernel(int E) {
    int e = blockIdx.x * blockDim.x + threadIdx.x;
    if (e >= E) return;
    int dst = g_dstbuf[e];
    int pos = atomicAdd(&g_cursor[dst], 1);
    if (pos < MAXE) g_csr[pos] = g_srcbuf[e];
}

// ---------------- agg layer 1 ----------------
__global__ void agg1_csr(const float* __restrict__ x) {
    int w    = (blockIdx.x * blockDim.x + threadIdx.x) >> 5;
    int lane = threadIdx.x & 31;
    if (w >= N_NODES) return;
    const int beg = g_row[w], end = g_row[w + 1];
    float4 a0 = {0.f, 0.f, 0.f, 0.f}, a1 = {0.f, 0.f, 0.f, 0.f};
    int i = beg;
    for (; i + 1 < end; i += 2) {
        int s0 = g_csr[i], s1 = g_csr[i + 1];
        float4 v0 = *reinterpret_cast<const float4*>(x + (size_t)s0 * CIN + lane * 4);
        float4 v1 = *reinterpret_cast<const float4*>(x + (size_t)s1 * CIN + lane * 4);
        a0.x += v0.x; a0.y += v0.y; a0.z += v0.z; a0.w += v0.w;
        a1.x += v1.x; a1.y += v1.y; a1.z += v1.z; a1.w += v1.w;
    }
    if (i < end) {
        int s0 = g_csr[i];
        float4 v0 = *reinterpret_cast<const float4*>(x + (size_t)s0 * CIN + lane * 4);
        a0.x += v0.x; a0.y += v0.y; a0.z += v0.z; a0.w += v0.w;
    }
    float rd = 1.0f / fmaxf((float)(end - beg), 1.0f);
    float4 o = {(a0.x + a1.x) * rd, (a0.y + a1.y) * rd,
                (a0.z + a1.z) * rd, (a0.w + a1.w) * rd};
    *reinterpret_cast<float4*>(g_mean1 + (size_t)w * CIN + lane * 4) = o;
}

// ---------------- agg layer 2 + final ----------------
__global__ void agg2_final(float* __restrict__ out) {
    int w    = (blockIdx.x * blockDim.x + threadIdx.x) >> 5;
    int lane = threadIdx.x & 31;
    if (w >= N_NODES) return;
    const int beg = g_row[w], end = g_row[w + 1];
    float2 a0 = {0.f, 0.f}, a1 = {0.f, 0.f};
    int i = beg;
    for (; i + 1 < end; i += 2) {
        int s0 = g_csr[i], s1 = g_csr[i + 1];
        float2 v0 = *reinterpret_cast<const float2*>(g_t + (size_t)s0 * COUT + lane * 2);
        float2 v1 = *reinterpret_cast<const float2*>(g_t + (size_t)s1 * COUT + lane * 2);
        a0.x += v0.x; a0.y += v0.y;
        a1.x += v1.x; a1.y += v1.y;
    }
    if (i < end) {
        int s0 = g_csr[i];
        float2 v0 = *reinterpret_cast<const float2*>(g_t + (size_t)s0 * COUT + lane * 2);
        a0.x += v0.x; a0.y += v0.y;
    }
    float rd = 1.0f / fmaxf((float)(end - beg), 1.0f);
    float2 r = *reinterpret_cast<const float2*>(g_r + (size_t)w * COUT + lane * 2);
    float2 o = {(a0.x + a1.x) * rd + r.x, (a0.y + a1.y) * rd + r.y};
    *reinterpret_cast<float2*>(out + (size_t)w * COUT + lane * 2) = o;
}

// ================= GEMM 1x: P = x @ W1r + b1 (K=128, side stream) =================
__global__ void __launch_bounds__(256) gemm1x_mma(const float* __restrict__ x,
                                                  const float* __restrict__ b1) {
    __shared__ uint32_t sAhi[64 * 20], sAlo[64 * 20];
    __shared__ uint32_t sBhi[128 * 20], sBlo[128 * 20];

    const int tid  = threadIdx.x;
    const int lane = tid & 31;
    const int wid  = tid >> 5;
    const int g    = lane >> 2;
    const int tig  = lane & 3;
    const int r0w  = (wid & 3) * 16;
    const int n0w  = (wid >> 2) * 64;
    const int block_m = blockIdx.x * 64;

    const int arow = tid >> 2;
    const int akq  = (tid & 3) * 8;
    const int anode = block_m + arow;
    const bool avalid = (anode < N_NODES);

    float acc[8][4];
#pragma unroll
    for (int nf = 0; nf < 8; nf++)
#pragma unroll
        for (int q = 0; q < 4; q++) acc[nf][q] = 0.f;

    for (int ch = 0; ch < 4; ch++) {
        const int kbase = ch * 32;
        {
            float v[8];
            if (avalid) {
                const float4* p = reinterpret_cast<const float4*>(
                    x + (size_t)anode * CIN + kbase + akq);
                float4 t0 = p[0], t1 = p[1];
                v[0]=t0.x; v[1]=t0.y; v[2]=t0.z; v[3]=t0.w;
                v[4]=t1.x; v[5]=t1.y; v[6]=t1.z; v[7]=t1.w;
            } else {
#pragma unroll
                for (int j = 0; j < 8; j++) v[j] = 0.f;
            }
            const int base = arow * 20 + (akq >> 1);
#pragma unroll
            for (int j = 0; j < 4; j++) {
                uint32_t hi, lo;
                bf16_split2(v[2*j], v[2*j+1], hi, lo);
                sAhi[base + j] = hi;
                sAlo[base + j] = lo;
            }
        }
        {
#pragma unroll
            for (int i = 0; i < 8; i++) {
                const int idx = tid + i * 256;
                const int n = idx >> 4, j = idx & 15;
                const int s = n * 20 + j;
                const int gsrc = n * 128 + 64 + ch * 16 + j;   // W1r half (kp 64..127)
                sBhi[s] = g_w1hi[gsrc];
                sBlo[s] = g_w1lo[gsrc];
            }
        }
        __syncthreads();

#pragma unroll
        for (int ks = 0; ks < 2; ks++) {
            const int kof = ks * 8;
            uint32_t ah[4], al[4];
            {
                const int i0 = (r0w + g) * 20 + kof + tig;
                const int i1 = (r0w + g + 8) * 20 + kof + tig;
                ah[0] = sAhi[i0];     ah[1] = sAhi[i1];
                ah[2] = sAhi[i0 + 4]; ah[3] = sAhi[i1 + 4];
                al[0] = sAlo[i0];     al[1] = sAlo[i1];
                al[2] = sAlo[i0 + 4]; al[3] = sAlo[i1 + 4];
            }
#pragma unroll
            for (int nf = 0; nf < 8; nf++) {
                const int nb = (n0w + nf * 8 + g) * 20 + kof + tig;
                uint32_t bh[2] = { sBhi[nb], sBhi[nb + 4] };
                uint32_t bl[2] = { sBlo[nb], sBlo[nb + 4] };
                mma_bf16(acc[nf], ah, bh);
                mma_bf16(acc[nf], ah, bl);
                mma_bf16(acc[nf], al, bh);
            }
        }
        __syncthreads();
    }

    const int row0 = block_m + r0w + g;
    const int row1 = row0 + 8;
#pragma unroll
    for (int nf = 0; nf < 8; nf++) {
        const int col = n0w + nf * 8 + 2 * tig;
        const float bb0 = b1[col], bb1 = b1[col + 1];
        if (row0 < N_NODES) {
            float2 o = {acc[nf][0] + bb0, acc[nf][1] + bb1};
            *reinterpret_cast<float2*>(g_p + (size_t)row0 * CHID + col) = o;
        }
        if (row1 < N_NODES) {
            float2 o = {acc[nf][2] + bb0, acc[nf][3] + bb1};
            *reinterpret_cast<float2*>(g_p + (size_t)row1 * CHID + col) = o;
        }
    }
}

// ================= GEMM 1m: h = relu(mean1 @ W1l + P) (K=128) =================
__global__ void __launch_bounds__(256) gemm1m_mma() {
    __shared__ uint32_t sAhi[64 * 20], sAlo[64 * 20];
    __shared__ uint32_t sBhi[128 * 20], sBlo[128 * 20];

    const int tid  = threadIdx.x;
    const int lane = tid & 31;
    const int wid  = tid >> 5;
    const int g    = lane >> 2;
    const int tig  = lane & 3;
    const int r0w  = (wid & 3) * 16;
    const int n0w  = (wid >> 2) * 64;
    const int block_m = blockIdx.x * 64;

    const int arow = tid >> 2;
    const int akq  = (tid & 3) * 8;
    const int anode = block_m + arow;
    const bool avalid = (anode < N_NODES);

    float acc[8][4];
#pragma unroll
    for (int nf = 0; nf < 8; nf++)
#pragma unroll
        for (int q = 0; q < 4; q++) acc[nf][q] = 0.f;

    for (int ch = 0; ch < 4; ch++) {
        const int kbase = ch * 32;
        {
            float v[8];
            if (avalid) {
                const float4* p = reinterpret_cast<const float4*>(
                    g_mean1 + (size_t)anode * CIN + kbase + akq);
                float4 t0 = p[0], t1 = p[1];
                v[0]=t0.x; v[1]=t0.y; v[2]=t0.z; v[3]=t0.w;
                v[4]=t1.x; v[5]=t1.y; v[6]=t1.z; v[7]=t1.w;
            } else {
#pragma unroll
                for (int j = 0; j < 8; j++) v[j] = 0.f;
            }
            const int base = arow * 20 + (akq >> 1);
#pragma unroll
            for (int j = 0; j < 4; j++) {
                uint32_t hi, lo;
                bf16_split2(v[2*j], v[2*j+1], hi, lo);
                sAhi[base + j] = hi;
                sAlo[base + j] = lo;
            }
        }
        {
#pragma unroll
            for (int i = 0; i < 8; i++) {
                const int idx = tid + i * 256;
                const int n = idx >> 4, j = idx & 15;
                const int s = n * 20 + j;
                const int gsrc = n * 128 + ch * 16 + j;   // W1l half (kp 0..63)
                sBhi[s] = g_w1hi[gsrc];
                sBlo[s] = g_w1lo[gsrc];
            }
        }
        __syncthreads();

#pragma unroll
        for (int ks = 0; ks < 2; ks++) {
            const int kof = ks * 8;
            uint32_t ah[4], al[4];
            {
                const int i0 = (r0w + g) * 20 + kof + tig;
                const int i1 = (r0w + g + 8) * 20 + kof + tig;
                ah[0] = sAhi[i0];     ah[1] = sAhi[i1];
                ah[2] = sAhi[i0 + 4]; ah[3] = sAhi[i1 + 4];
                al[0] = sAlo[i0];     al[1] = sAlo[i1];
                al[2] = sAlo[i0 + 4]; al[3] = sAlo[i1 + 4];
            }
#pragma unroll
            for (int nf = 0; nf < 8; nf++) {
                const int nb = (n0w + nf * 8 + g) * 20 + kof + tig;
                uint32_t bh[2] = { sBhi[nb], sBhi[nb + 4] };
                uint32_t bl[2] = { sBlo[nb], sBlo[nb + 4] };
                mma_bf16(acc[nf], ah, bh);
                mma_bf16(acc[nf], ah, bl);
                mma_bf16(acc[nf], al, bh);
            }
        }
        __syncthreads();
    }

    const int row0 = block_m + r0w + g;
    const int row1 = row0 + 8;
#pragma unroll
    for (int nf = 0; nf < 8; nf++) {
        const int col = n0w + nf * 8 + 2 * tig;
        if (row0 < N_NODES) {
            float2 p = *reinterpret_cast<const float2*>(g_p + (size_t)row0 * CHID + col);
            float2 o = {fmaxf(acc[nf][0] + p.x, 0.f), fmaxf(acc[nf][1] + p.y, 0.f)};
            *reinterpret_cast<float2*>(g_h + (size_t)row0 * CHID + col) = o;
        }
        if (row1 < N_NODES) {
            float2 p = *reinterpret_cast<const float2*>(g_p + (size_t)row1 * CHID + col);
            float2 o = {fmaxf(acc[nf][2] + p.x, 0.f), fmaxf(acc[nf][3] + p.y, 0.f)};
            *reinterpret_cast<float2*>(g_h + (size_t)row1 * CHID + col) = o;
        }
    }
}

// ================= GEMM layer 2 (R12, unchanged) =================
__global__ void __launch_bounds__(256) gemm2_mma(const float* __restrict__ b2) {
    __shared__ uint32_t sAhi[64 * 20], sAlo[64 * 20];
    __shared__ uint32_t sBhi[128 * 20], sBlo[128 * 20];

    const int tid  = threadIdx.x;
    const int lane = tid & 31;
    const int wid  = tid >> 5;
    const int g    = lane >> 2;
    const int tig  = lane & 3;
    const int r0w  = (wid & 3) * 16;
    const int n0w  = (wid >> 2) * 64;
    const int block_m = blockIdx.x * 64;

    const int arow = tid >> 2;
    const int akq  = (tid & 3) * 8;
    const int anode = block_m + arow;
    const bool avalid = (anode < N_NODES);

    float acc[8][4];
#pragma unroll
    for (int nf = 0; nf < 8; nf++)
#pragma unroll
        for (int q = 0; q < 4; q++) acc[nf][q] = 0.f;

    for (int ch = 0; ch < 4; ch++) {
        const int kbase = ch * 32;
        {
            float v[8];
            if (avalid) {
                const float4* p = reinterpret_cast<const float4*>(
                    g_h + (size_t)anode * CHID + kbase + akq);
                float4 t0 = p[0], t1 = p[1];
                v[0]=t0.x; v[1]=t0.y; v[2]=t0.z; v[3]=t0.w;
                v[4]=t1.x; v[5]=t1.y; v[6]=t1.z; v[7]=t1.w;
            } else {
#pragma unroll
                for (int j = 0; j < 8; j++) v[j] = 0.f;
            }
            const int base = arow * 20 + (akq >> 1);
#pragma unroll
            for (int j = 0; j < 4; j++) {
                uint32_t hi, lo;
                bf16_split2(v[2*j], v[2*j+1], hi, lo);
                sAhi[base + j] = hi;
                sAlo[base + j] = lo;
            }
        }
        {
#pragma unroll
            for (int i = 0; i < 8; i++) {
                const int idx = tid + i * 256;
                const int n = idx >> 4, j = idx & 15;
                const int s = n * 20 + j;
                const int gsrc = n * 64 + ch * 16 + j;
                sBhi[s] = g_w2hi[gsrc];
                sBlo[s] = g_w2lo[gsrc];
            }
        }
        __syncthreads();

#pragma unroll
        for (int ks = 0; ks < 2; ks++) {
            const int kof = ks * 8;
            uint32_t ah[4], al[4];
            {
                const int i0 = (r0w + g) * 20 + kof + tig;
                const int i1 = (r0w + g + 8) * 20 + kof + tig;
                ah[0] = sAhi[i0];     ah[1] = sAhi[i1];
                ah[2] = sAhi[i0 + 4]; ah[3] = sAhi[i1 + 4];
                al[0] = sAlo[i0];     al[1] = sAlo[i1];
                al[2] = sAlo[i0 + 4]; al[3] = sAlo[i1 + 4];
            }
#pragma unroll
            for (int nf = 0; nf < 8; nf++) {
                const int nb = (n0w + nf * 8 + g) * 20 + kof + tig;
                uint32_t bh[2] = { sBhi[nb], sBhi[nb + 4] };
                uint32_t bl[2] = { sBlo[nb], sBlo[nb + 4] };
                mma_bf16(acc[nf], ah, bh);
                mma_bf16(acc[nf], ah, bl);
                mma_bf16(acc[nf], al, bh);
            }
        }
        __syncthreads();
    }

    const int row0 = block_m + r0w + g;
    const int row1 = row0 + 8;
#pragma unroll
    for (int nf = 0; nf < 8; nf++) {
        const int col = n0w + nf * 8 + 2 * tig;
        if (col < 64) {
            if (row0 < N_NODES) {
                float2 o = {acc[nf][0], acc[nf][1]};
                *reinterpret_cast<float2*>(g_t + (size_t)row0 * COUT + col) = o;
            }
            if (row1 < N_NODES) {
                float2 o = {acc[nf][2], acc[nf][3]};
                *reinterpret_cast<float2*>(g_t + (size_t)row1 * COUT + col) = o;
            }
        } else {
            const int cc = col - 64;
            const float bb0 = b2[cc], bb1 = b2[cc + 1];
            if (row0 < N_NODES) {
                float2 o = {acc[nf][0] + bb0, acc[nf][1] + bb1};
                *reinterpret_cast<float2*>(g_r + (size_t)row0 * COUT + cc) = o;
            }
            if (row1 < N_NODES) {
                float2 o = {acc[nf][2] + bb0, acc[nf][3] + bb1};
                *reinterpret_cast<float2*>(g_r + (size_t)row1 * COUT + cc) = o;
            }
        }
    }
}

// ---------------- launch ----------------
extern "C" void kernel_launch(void* const* d_in, const int* in_sizes, int n_in,
                              void* d_out, int out_size) {
    const float* x   = (const float*)d_in[0];
    const void*  ei  = d_in[1];
    const float* W1l = (const float*)d_in[2];
    const float* W1r = (const float*)d_in[3];
    const float* b1  = (const float*)d_in[4];
    const float* W2l = (const float*)d_in[5];
    const float* W2r = (const float*)d_in[6];
    const float* b2  = (const float*)d_in[7];
    float* out = (float*)d_out;

    const int E = in_sizes[1] / 2;

    // lazily created once (outside any capture: first call is the correctness run)
    static cudaStream_t sB = nullptr;
    static cudaEvent_t evF = nullptr, evJ = nullptr;
    if (sB == nullptr) {
        cudaStreamCreateWithFlags(&sB, cudaStreamNonBlocking);
        cudaEventCreateWithFlags(&evF, cudaEventDisableTiming);
        cudaEventCreateWithFlags(&evJ, cudaEventDisableTiming);
    }

    // ---- fork: side stream does W prep + the graph-independent half of layer 1 ----
    cudaEventRecord(evF, 0);
    cudaStreamWaitEvent(sB, evF, 0);
    prep_w1<<<64, 256, 0, sB>>>(W1l, W1r);
    prep_w2<<<32, 256, 0, sB>>>(W2l, W2r);
    {
        int blocks = (N_NODES + 63) / 64;
        gemm1x_mma<<<blocks, 256, 0, sB>>>(x, b1);
    }
    cudaEventRecord(evJ, sB);

    // ---- main stream: CSR build + aggregation ----
    {
        int blocks = (N_NODES + 255) / 256;
        zero_deg<<<blocks, 256>>>();
    }
    {
        long long n64_safe = (long long)E / 2;
        detect_kernel<<<1024, 256>>>((const long long*)ei, n64_safe);
    }
    {
        int blocks = (E + 255) / 256;
        decode_count<<<blocks, 256>>>(ei, E);
        block_sum_kernel<<<SCAN_BLOCKS, 256>>>();
        scan_bsum_kernel<<<1, 512>>>();
        block_scan_kernel<<<SCAN_BLOCKS, 256>>>();
        scatter_kernel<<<blocks, 256>>>(E);
    }
    {
        long long threads = (long long)N_NODES * 32;
        int blocks = (int)((threads + 255) / 256);
        agg1_csr<<<blocks, 256>>>(x);
    }

    // ---- join, then the dependent half of layer 1 and the rest ----
    cudaStreamWaitEvent(0, evJ, 0);
    {
        int blocks = (N_NODES + 63) / 64;
        gemm1m_mma<<<blocks, 256>>>();
        gemm2_mma<<<blocks, 256>>>(b2);
    }
    {
        long long threads = (long long)N_NODES * 32;
        int blocks = (int)((threads + 255) / 256);
        agg2_final<<<blocks, 256>>>(out);
    }
}

// round 15
// speedup vs baseline: 1.0415x; 1.0415x over previous
#include <cuda_runtime.h>
#include <cuda_bf16.h>
#include <cuda_fp16.h>
#include <cstdint>

#define N_NODES 100000
#define CIN 128
#define CHID 128
#define COUT 64
#define MAXE 1600000
#define SCAN_BLOCKS ((N_NODES + 255) / 256)

// ---------------- scratch ----------------
__device__ __align__(16) float  g_mean1[(size_t)N_NODES * CIN];
__device__ __align__(16) float  g_h    [(size_t)N_NODES * CHID];
__device__ __align__(16) __half g_th   [(size_t)N_NODES * COUT];   // t = h @ W2l (fp16)
__device__ __align__(16) float  g_r    [(size_t)N_NODES * COUT];
__device__ __align__(16) __half g_xh   [(size_t)N_NODES * CIN];    // fp16 copy of x
__device__ int g_degi  [N_NODES];
__device__ int g_row   [N_NODES + 1];
__device__ int g_cursor[N_NODES];
__device__ int g_srcbuf[MAXE];
__device__ int g_dstbuf[MAXE];
__device__ int g_csr   [MAXE];
__device__ int g_bsum  [512];
__device__ int g_is64;
// pre-split weights, transposed [n][kpair] u32 (bf16x2)
__device__ __align__(16) uint32_t g_w1hi[128 * 128];
__device__ __align__(16) uint32_t g_w1lo[128 * 128];
__device__ __align__(16) uint32_t g_w2hi[128 * 64];
__device__ __align__(16) uint32_t g_w2lo[128 * 64];

// ---------------- bf16 split helpers ----------------
__device__ __forceinline__ void bf16_split2(float f0, float f1,
                                            uint32_t& hi, uint32_t& lo) {
    __nv_bfloat16 h0 = __float2bfloat16(f0);
    __nv_bfloat16 h1 = __float2bfloat16(f1);
    float r0 = f0 - __bfloat162float(h0);
    float r1 = f1 - __bfloat162float(h1);
    __nv_bfloat16 l0 = __float2bfloat16(r0);
    __nv_bfloat16 l1 = __float2bfloat16(r1);
    hi = ((uint32_t)__bfloat16_as_ushort(h1) << 16) | __bfloat16_as_ushort(h0);
    lo = ((uint32_t)__bfloat16_as_ushort(l1) << 16) | __bfloat16_as_ushort(l0);
}

__device__ __forceinline__ void mma_bf16(float* d, const uint32_t* a,
                                         const uint32_t* b) {
    asm volatile(
        "mma.sync.aligned.m16n8k16.row.col.f32.bf16.bf16.f32 "
        "{%0,%1,%2,%3}, {%4,%5,%6,%7}, {%8,%9}, {%0,%1,%2,%3};"
        : "+f"(d[0]), "+f"(d[1]), "+f"(d[2]), "+f"(d[3])
        : "r"(a[0]), "r"(a[1]), "r"(a[2]), "r"(a[3]), "r"(b[0]), "r"(b[1]));
}

// ---------------- prep: pre-split W1/W2 ----------------
__global__ void prep_w1(const float* __restrict__ W1l,
                        const float* __restrict__ W1r) {
    int idx = blockIdx.x * blockDim.x + threadIdx.x;
    if (idx >= 128 * 128) return;
    int n = idx >> 7, kp = idx & 127;
    int k0 = 2 * kp;
    float a = (k0 < 128) ? W1l[(size_t)k0 * 128 + n] : W1r[(size_t)(k0 - 128) * 128 + n];
    float c = (k0 + 1 < 128) ? W1l[(size_t)(k0 + 1) * 128 + n]
                             : W1r[(size_t)(k0 + 1 - 128) * 128 + n];
    uint32_t hi, lo;
    bf16_split2(a, c, hi, lo);
    g_w1hi[idx] = hi;
    g_w1lo[idx] = lo;
}

__global__ void prep_w2(const float* __restrict__ W2l,
                        const float* __restrict__ W2r) {
    int idx = blockIdx.x * blockDim.x + threadIdx.x;
    if (idx >= 128 * 64) return;
    int n = idx >> 6, kp = idx & 63;
    int k0 = 2 * kp;
    const float* wb = (n < 64) ? (W2l + n) : (W2r + (n - 64));
    float a = wb[(size_t)k0 * 64];
    float c = wb[(size_t)(k0 + 1) * 64];
    uint32_t hi, lo;
    bf16_split2(a, c, hi, lo);
    g_w2hi[idx] = hi;
    g_w2lo[idx] = lo;
}

// ---------------- conv_x: x -> fp16 plane ----------------
__global__ void conv_x(const float* __restrict__ x) {
    int i = blockIdx.x * blockDim.x + threadIdx.x;
    if (i >= N_NODES * (CIN / 4)) return;
    float4 v = reinterpret_cast<const float4*>(x)[i];
    __half2* dst = reinterpret_cast<__half2*>(g_xh);
    dst[2 * i]     = __floats2half2_rn(v.x, v.y);
    dst[2 * i + 1] = __floats2half2_rn(v.z, v.w);
}

// ---------------- zero deg + init flag ----------------
__global__ void zero_deg() {
    int i = blockIdx.x * blockDim.x + threadIdx.x;
    if (i < N_NODES) g_degi[i] = 0;
    if (i == 0) g_is64 = 1;
}

// ---------------- detect edge_index dtype ----------------
__global__ void detect_kernel(const long long* __restrict__ ei, long long n) {
    long long i = (long long)blockIdx.x * blockDim.x + threadIdx.x;
    long long stride = (long long)gridDim.x * blockDim.x;
    for (; i < n; i += stride) {
        unsigned long long v = (unsigned long long)ei[i];
        if (v >= (unsigned long long)N_NODES) { g_is64 = 0; return; }
    }
}

// ---------------- decode edges + degree histogram ----------------
__global__ void decode_count(const void* __restrict__ ei_raw, int E) {
    int e = blockIdx.x * blockDim.x + threadIdx.x;
    if (e >= E) return;
    int src, dst;
    if (g_is64) {
        const long long* ei = (const long long*)ei_raw;
        src = (int)ei[e]; dst = (int)ei[(size_t)E + e];
    } else {
        const int* ei = (const int*)ei_raw;
        src = ei[e]; dst = ei[(size_t)E + e];
    }
    if ((unsigned)src >= N_NODES) src = 0;
    if ((unsigned)dst >= N_NODES) dst = 0;
    g_srcbuf[e] = src;
    g_dstbuf[e] = dst;
    atomicAdd(&g_degi[dst], 1);
}

// ---------------- scan phases ----------------
__global__ void block_sum_kernel() {
    int i = blockIdx.x * 256 + threadIdx.x;
    int v = (i < N_NODES) ? g_degi[i] : 0;
#pragma unroll
    for (int o = 16; o; o >>= 1) v += __shfl_down_sync(0xffffffffu, v, o);
    __shared__ int ws[8];
    if ((threadIdx.x & 31) == 0) ws[threadIdx.x >> 5] = v;
    __syncthreads();
    if (threadIdx.x < 8) {
        int s = ws[threadIdx.x];
#pragma unroll
        for (int o = 4; o; o >>= 1) s += __shfl_down_sync(0xffu, s, o);
        if (threadIdx.x == 0) g_bsum[blockIdx.x] = s;
    }
}

__global__ void scan_bsum_kernel() {
    __shared__ int sp[512];
    int tid = threadIdx.x;
    int v = (tid < SCAN_BLOCKS) ? g_bsum[tid] : 0;
    sp[tid] = v;
    __syncthreads();
    for (int off = 1; off < 512; off <<= 1) {
        int t = (tid >= off) ? sp[tid - off] : 0;
        __syncthreads();
        sp[tid] += t;
        __syncthreads();
    }
    if (tid < SCAN_BLOCKS) g_bsum[tid] = sp[tid] - v;
    if (tid == SCAN_BLOCKS - 1) g_row[N_NODES] = sp[tid];
}

__global__ void block_scan_kernel() {
    int i = blockIdx.x * 256 + threadIdx.x;
    int lane = threadIdx.x & 31, warp = threadIdx.x >> 5;
    int v = (i < N_NODES) ? g_degi[i] : 0;
    int s = v;
#pragma unroll
    for (int o = 1; o < 32; o <<= 1) {
        int t = __shfl_up_sync(0xffffffffu, s, o);
        if (lane >= o) s += t;
    }
    __shared__ int ws[8];
    if (lane == 31) ws[warp] = s;
    __syncthreads();
    if (threadIdx.x == 0) {
        int run = 0;
#pragma unroll
        for (int w = 0; w < 8; w++) { int t = ws[w]; ws[w] = run; run += t; }
    }
    __syncthreads();
    int excl = (s - v) + ws[warp] + g_bsum[blockIdx.x];
    if (i < N_NODES) { g_row[i] = excl; g_cursor[i] = excl; }
}

__global__ void scatter_kernel(int E) {
    int e = blockIdx.x * blockDim.x + threadIdx.x;
    if (e >= E) return;
    int dst = g_dstbuf[e];
    int pos = atomicAdd(&g_cursor[dst], 1);
    if (pos < MAXE) g_csr[pos] = g_srcbuf[e];
}

// ---------------- agg layer 1: mean of fp16 x over in-neighbors ----------------
__global__ void agg1_csr() {
    int w    = (blockIdx.x * blockDim.x + threadIdx.x) >> 5;
    int lane = threadIdx.x & 31;
    if (w >= N_NODES) return;
    const int beg = g_row[w], end = g_row[w + 1];
    float4 a0 = {0.f, 0.f, 0.f, 0.f}, a1 = {0.f, 0.f, 0.f, 0.f};
    int i = beg;
    for (; i + 1 < end; i += 2) {
        int s0 = g_csr[i], s1 = g_csr[i + 1];
        const __half2* p0 = reinterpret_cast<const __half2*>(g_xh + (size_t)s0 * CIN) + lane * 2;
        const __half2* p1 = reinterpret_cast<const __half2*>(g_xh + (size_t)s1 * CIN) + lane * 2;
        __half2 u0 = p0[0], u1 = p0[1];
        __half2 w0 = p1[0], w1 = p1[1];
        float2 f0 = __half22float2(u0), f1 = __half22float2(u1);
        float2 e0 = __half22float2(w0), e1 = __half22float2(w1);
        a0.x += f0.x; a0.y += f0.y; a0.z += f1.x; a0.w += f1.y;
        a1.x += e0.x; a1.y += e0.y; a1.z += e1.x; a1.w += e1.y;
    }
    if (i < end) {
        int s0 = g_csr[i];
        const __half2* p0 = reinterpret_cast<const __half2*>(g_xh + (size_t)s0 * CIN) + lane * 2;
        __half2 u0 = p0[0], u1 = p0[1];
        float2 f0 = __half22float2(u0), f1 = __half22float2(u1);
        a0.x += f0.x; a0.y += f0.y; a0.z += f1.x; a0.w += f1.y;
    }
    float rd = 1.0f / fmaxf((float)(end - beg), 1.0f);
    float4 o = {(a0.x + a1.x) * rd, (a0.y + a1.y) * rd,
                (a0.z + a1.z) * rd, (a0.w + a1.w) * rd};
    *reinterpret_cast<float4*>(g_mean1 + (size_t)w * CIN + lane * 4) = o;
}

// ---------------- agg layer 2 + final: out = mean(t_fp16) + r ----------------
__global__ void agg2_final(float* __restrict__ out) {
    int w    = (blockIdx.x * blockDim.x + threadIdx.x) >> 5;
    int lane = threadIdx.x & 31;
    if (w >= N_NODES) return;
    const int beg = g_row[w], end = g_row[w + 1];
    const __half2* th = reinterpret_cast<const __half2*>(g_th);
    float2 a0 = {0.f, 0.f}, a1 = {0.f, 0.f};
    int i = beg;
    for (; i + 1 < end; i += 2) {
        int s0 = g_csr[i], s1 = g_csr[i + 1];
        float2 v0 = __half22float2(th[(size_t)s0 * 32 + lane]);
        float2 v1 = __half22float2(th[(size_t)s1 * 32 + lane]);
        a0.x += v0.x; a0.y += v0.y;
        a1.x += v1.x; a1.y += v1.y;
    }
    if (i < end) {
        int s0 = g_csr[i];
        float2 v0 = __half22float2(th[(size_t)s0 * 32 + lane]);
        a0.x += v0.x; a0.y += v0.y;
    }
    float rd = 1.0f / fmaxf((float)(end - beg), 1.0f);
    float2 r = *reinterpret_cast<const float2*>(g_r + (size_t)w * COUT + lane * 2);
    float2 o = {(a0.x + a1.x) * rd + r.x, (a0.y + a1.y) * rd + r.y};
    *reinterpret_cast<float2*>(out + (size_t)w * COUT + lane * 2) = o;
}

// ================= GEMM layer 1 (R12, unchanged) =================
__global__ void __launch_bounds__(256) gemm1_mma(const float* __restrict__ x,
                                                 const float* __restrict__ b1) {
    __shared__ uint32_t sAhi[64 * 20], sAlo[64 * 20];
    __shared__ uint32_t sBhi[128 * 20], sBlo[128 * 20];

    const int tid  = threadIdx.x;
    const int lane = tid & 31;
    const int wid  = tid >> 5;
    const int g    = lane >> 2;
    const int tig  = lane & 3;
    const int r0w  = (wid & 3) * 16;
    const int n0w  = (wid >> 2) * 64;
    const int block_m = blockIdx.x * 64;

    const int arow = tid >> 2;
    const int akq  = (tid & 3) * 8;
    const int anode = block_m + arow;
    const bool avalid = (anode < N_NODES);

    float acc[8][4];
#pragma unroll
    for (int nf = 0; nf < 8; nf++)
#pragma unroll
        for (int q = 0; q < 4; q++) acc[nf][q] = 0.f;

    for (int ch = 0; ch < 8; ch++) {
        const int kbase = ch * 32;
        {
            float v[8];
            if (avalid) {
                const float* src = (kbase < 128)
                    ? (g_mean1 + (size_t)anode * CIN + kbase + akq)
                    : (x + (size_t)anode * CIN + (kbase - 128) + akq);
                const float4* p = reinterpret_cast<const float4*>(src);
                float4 t0 = p[0], t1 = p[1];
                v[0]=t0.x; v[1]=t0.y; v[2]=t0.z; v[3]=t0.w;
                v[4]=t1.x; v[5]=t1.y; v[6]=t1.z; v[7]=t1.w;
            } else {
#pragma unroll
                for (int j = 0; j < 8; j++) v[j] = 0.f;
            }
            const int base = arow * 20 + (akq >> 1);
#pragma unroll
            for (int j = 0; j < 4; j++) {
                uint32_t hi, lo;
                bf16_split2(v[2*j], v[2*j+1], hi, lo);
                sAhi[base + j] = hi;
                sAlo[base + j] = lo;
            }
        }
        {
#pragma unroll
            for (int i = 0; i < 8; i++) {
                const int idx = tid + i * 256;
                const int n = idx >> 4, j = idx & 15;
                const int s = n * 20 + j;
                const int gsrc = n * 128 + ch * 16 + j;
                sBhi[s] = g_w1hi[gsrc];
                sBlo[s] = g_w1lo[gsrc];
            }
        }
        __syncthreads();

#pragma unroll
        for (int ks = 0; ks < 2; ks++) {
            const int kof = ks * 8;
            uint32_t ah[4], al[4];
            {
                const int i0 = (r0w + g) * 20 + kof + tig;
                const int i1 = (r0w + g + 8) * 20 + kof + tig;
                ah[0] = sAhi[i0];     ah[1] = sAhi[i1];
                ah[2] = sAhi[i0 + 4]; ah[3] = sAhi[i1 + 4];
                al[0] = sAlo[i0];     al[1] = sAlo[i1];
                al[2] = sAlo[i0 + 4]; al[3] = sAlo[i1 + 4];
            }
#pragma unroll
            for (int nf = 0; nf < 8; nf++) {
                const int nb = (n0w + nf * 8 + g) * 20 + kof + tig;
                uint32_t bh[2] = { sBhi[nb], sBhi[nb + 4] };
                uint32_t bl[2] = { sBlo[nb], sBlo[nb + 4] };
                mma_bf16(acc[nf], ah, bh);
                mma_bf16(acc[nf], ah, bl);
                mma_bf16(acc[nf], al, bh);
            }
        }
        __syncthreads();
    }

    const int row0 = block_m + r0w + g;
    const int row1 = row0 + 8;
#pragma unroll
    for (int nf = 0; nf < 8; nf++) {
        const int col = n0w + nf * 8 + 2 * tig;
        const float bb0 = b1[col], bb1 = b1[col + 1];
        if (row0 < N_NODES) {
            float2 o = {fmaxf(acc[nf][0] + bb0, 0.f), fmaxf(acc[nf][1] + bb1, 0.f)};
            *reinterpret_cast<float2*>(g_h + (size_t)row0 * CHID + col) = o;
        }
        if (row1 < N_NODES) {
            float2 o = {fmaxf(acc[nf][2] + bb0, 0.f), fmaxf(acc[nf][3] + bb1, 0.f)};
            *reinterpret_cast<float2*>(g_h + (size_t)row1 * CHID + col) = o;
        }
    }
}

// ================= GEMM layer 2 (R12 body; t stored as fp16) =================
__global__ void __launch_bounds__(256) gemm2_mma(const float* __restrict__ b2) {
    __shared__ uint32_t sAhi[64 * 20], sAlo[64 * 20];
    __shared__ uint32_t sBhi[128 * 20], sBlo[128 * 20];

    const int tid  = threadIdx.x;
    const int lane = tid & 31;
    const int wid  = tid >> 5;
    const int g    = lane >> 2;
    const int tig  = lane & 3;
    const int r0w  = (wid & 3) * 16;
    const int n0w  = (wid >> 2) * 64;
    const int block_m = blockIdx.x * 64;

    const int arow = tid >> 2;
    const int akq  = (tid & 3) * 8;
    const int anode = block_m + arow;
    const bool avalid = (anode < N_NODES);

    float acc[8][4];
#pragma unroll
    for (int nf = 0; nf < 8; nf++)
#pragma unroll
        for (int q = 0; q < 4; q++) acc[nf][q] = 0.f;

    for (int ch = 0; ch < 4; ch++) {
        const int kbase = ch * 32;
        {
            float v[8];
            if (avalid) {
                const float4* p = reinterpret_cast<const float4*>(
                    g_h + (size_t)anode * CHID + kbase + akq);
                float4 t0 = p[0], t1 = p[1];
                v[0]=t0.x; v[1]=t0.y; v[2]=t0.z; v[3]=t0.w;
                v[4]=t1.x; v[5]=t1.y; v[6]=t1.z; v[7]=t1.w;
            } else {
#pragma unroll
                for (int j = 0; j < 8; j++) v[j] = 0.f;
            }
            const int base = arow * 20 + (akq >> 1);
#pragma unroll
            for (int j = 0; j < 4; j++) {
                uint32_t hi, lo;
                bf16_split2(v[2*j], v[2*j+1], hi, lo);
                sAhi[base + j] = hi;
                sAlo[base + j] = lo;
            }
        }
        {
#pragma unroll
            for (int i = 0; i < 8; i++) {
                const int idx = tid + i * 256;
                const int n = idx >> 4, j = idx & 15;
                const int s = n * 20 + j;
                const int gsrc = n * 64 + ch * 16 + j;
                sBhi[s] = g_w2hi[gsrc];
                sBlo[s] = g_w2lo[gsrc];
            }
        }
        __syncthreads();

#pragma unroll
        for (int ks = 0; ks < 2; ks++) {
            const int kof = ks * 8;
            uint32_t ah[4], al[4];
            {
                const int i0 = (r0w + g) * 20 + kof + tig;
                const int i1 = (r0w + g + 8) * 20 + kof + tig;
                ah[0] = sAhi[i0];     ah[1] = sAhi[i1];
                ah[2] = sAhi[i0 + 4]; ah[3] = sAhi[i1 + 4];
                al[0] = sAlo[i0];     al[1] = sAlo[i1];
                al[2] = sAlo[i0 + 4]; al[3] = sAlo[i1 + 4];
            }
#pragma unroll
            for (int nf = 0; nf < 8; nf++) {
                const int nb = (n0w + nf * 8 + g) * 20 + kof + tig;
                uint32_t bh[2] = { sBhi[nb], sBhi[nb + 4] };
                uint32_t bl[2] = { sBlo[nb], sBlo[nb + 4] };
                mma_bf16(acc[nf], ah, bh);
                mma_bf16(acc[nf], ah, bl);
                mma_bf16(acc[nf], al, bh);
            }
        }
        __syncthreads();
    }

    const int row0 = block_m + r0w + g;
    const int row1 = row0 + 8;
#pragma unroll
    for (int nf = 0; nf < 8; nf++) {
        const int col = n0w + nf * 8 + 2 * tig;
        if (col < 64) {
            if (row0 < N_NODES) {
                __half2 o = __floats2half2_rn(acc[nf][0], acc[nf][1]);
                *reinterpret_cast<__half2*>(g_th + (size_t)row0 * COUT + col) = o;
            }
            if (row1 < N_NODES) {
                __half2 o = __floats2half2_rn(acc[nf][2], acc[nf][3]);
                *reinterpret_cast<__half2*>(g_th + (size_t)row1 * COUT + col) = o;
            }
        } else {
            const int cc = col - 64;
            const float bb0 = b2[cc], bb1 = b2[cc + 1];
            if (row0 < N_NODES) {
                float2 o = {acc[nf][0] + bb0, acc[nf][1] + bb1};
                *reinterpret_cast<float2*>(g_r + (size_t)row0 * COUT + cc) = o;
            }
            if (row1 < N_NODES) {
                float2 o = {acc[nf][2] + bb0, acc[nf][3] + bb1};
                *reinterpret_cast<float2*>(g_r + (size_t)row1 * COUT + cc) = o;
            }
        }
    }
}

// ---------------- launch ----------------
extern "C" void kernel_launch(void* const* d_in, const int* in_sizes, int n_in,
                              void* d_out, int out_size) {
    const float* x   = (const float*)d_in[0];
    const void*  ei  = d_in[1];
    const float* W1l = (const float*)d_in[2];
    const float* W1r = (const float*)d_in[3];
    const float* b1  = (const float*)d_in[4];
    const float* W2l = (const float*)d_in[5];
    const float* W2r = (const float*)d_in[6];
    const float* b2  = (const float*)d_in[7];
    float* out = (float*)d_out;

    const int E = in_sizes[1] / 2;

    {
        int blocks = (N_NODES + 255) / 256;
        zero_deg<<<blocks, 256>>>();
        prep_w1<<<64, 256>>>(W1l, W1r);
        prep_w2<<<32, 256>>>(W2l, W2r);
    }
    {
        int blocks = (N_NODES * (CIN / 4) + 255) / 256;
        conv_x<<<blocks, 256>>>(x);
    }
    {
        long long n64_safe = (long long)E / 2;
        detect_kernel<<<1024, 256>>>((const long long*)ei, n64_safe);
    }
    {
        int blocks = (E + 255) / 256;
        decode_count<<<blocks, 256>>>(ei, E);
        block_sum_kernel<<<SCAN_BLOCKS, 256>>>();
        scan_bsum_kernel<<<1, 512>>>();
        block_scan_kernel<<<SCAN_BLOCKS, 256>>>();
        scatter_kernel<<<blocks, 256>>>(E);
    }
    {
        long long threads = (long long)N_NODES * 32;
        int blocks = (int)((threads + 255) / 256);
        agg1_csr<<<blocks, 256>>>();
    }
    {
        int blocks = (N_NODES + 63) / 64;
        gemm1_mma<<<blocks, 256>>>(x, b1);
        gemm2_mma<<<blocks, 256>>>(b2);
    }
    {
        long long threads = (long long)N_NODES * 32;
        int blocks = (int)((threads + 255) / 256);
        agg2_final<<<blocks, 256>>>(out);
    }
}

// round 16
// speedup vs baseline: 1.0419x; 1.0004x over previous
#include <cuda_runtime.h>
#include <cuda_bf16.h>
#include <cuda_fp16.h>
#include <cstdint>

#define N_NODES 100000
#define CIN 128
#define CHID 128
#define COUT 64
#define MAXE 1600000
#define SCAN_BLOCKS ((N_NODES + 255) / 256)

// ---------------- scratch ----------------
__device__ __align__(16) float  g_mean1[(size_t)N_NODES * CIN];
__device__ __align__(16) float  g_h    [(size_t)N_NODES * CHID];
__device__ __align__(16) __half g_th   [(size_t)N_NODES * COUT];   // t = h @ W2l (fp16)
__device__ __align__(16) float  g_r    [(size_t)N_NODES * COUT];
__device__ __align__(16) __half g_xh   [(size_t)N_NODES * CIN];    // fp16 copy of x
__device__ int g_degi  [N_NODES];
__device__ int g_row   [N_NODES + 1];
__device__ int g_cursor[N_NODES];
__device__ int g_srcbuf[MAXE];
__device__ int g_dstbuf[MAXE];
__device__ int g_csr   [MAXE];
__device__ int g_bsum  [512];
__device__ int g_is64;
// pre-split weights, transposed [n][kpair] u32 (bf16x2)
__device__ __align__(16) uint32_t g_w1hi[128 * 128];
__device__ __align__(16) uint32_t g_w1lo[128 * 128];
__device__ __align__(16) uint32_t g_w2hi[128 * 64];
__device__ __align__(16) uint32_t g_w2lo[128 * 64];

// ---------------- bf16 split helpers ----------------
__device__ __forceinline__ void bf16_split2(float f0, float f1,
                                            uint32_t& hi, uint32_t& lo) {
    __nv_bfloat16 h0 = __float2bfloat16(f0);
    __nv_bfloat16 h1 = __float2bfloat16(f1);
    float r0 = f0 - __bfloat162float(h0);
    float r1 = f1 - __bfloat162float(h1);
    __nv_bfloat16 l0 = __float2bfloat16(r0);
    __nv_bfloat16 l1 = __float2bfloat16(r1);
    hi = ((uint32_t)__bfloat16_as_ushort(h1) << 16) | __bfloat16_as_ushort(h0);
    lo = ((uint32_t)__bfloat16_as_ushort(l1) << 16) | __bfloat16_as_ushort(l0);
}

__device__ __forceinline__ void mma_bf16(float* d, const uint32_t* a,
                                         const uint32_t* b) {
    asm volatile(
        "mma.sync.aligned.m16n8k16.row.col.f32.bf16.bf16.f32 "
        "{%0,%1,%2,%3}, {%4,%5,%6,%7}, {%8,%9}, {%0,%1,%2,%3};"
        : "+f"(d[0]), "+f"(d[1]), "+f"(d[2]), "+f"(d[3])
        : "r"(a[0]), "r"(a[1]), "r"(a[2]), "r"(a[3]), "r"(b[0]), "r"(b[1]));
}

// ---------------- prep: pre-split W1/W2 ----------------
__global__ void prep_w1(const float* __restrict__ W1l,
                        const float* __restrict__ W1r) {
    int idx = blockIdx.x * blockDim.x + threadIdx.x;
    if (idx >= 128 * 128) return;
    int n = idx >> 7, kp = idx & 127;
    int k0 = 2 * kp;
    float a = (k0 < 128) ? W1l[(size_t)k0 * 128 + n] : W1r[(size_t)(k0 - 128) * 128 + n];
    float c = (k0 + 1 < 128) ? W1l[(size_t)(k0 + 1) * 128 + n]
                             : W1r[(size_t)(k0 + 1 - 128) * 128 + n];
    uint32_t hi, lo;
    bf16_split2(a, c, hi, lo);
    g_w1hi[idx] = hi;
    g_w1lo[idx] = lo;
}

__global__ void prep_w2(const float* __restrict__ W2l,
                        const float* __restrict__ W2r) {
    int idx = blockIdx.x * blockDim.x + threadIdx.x;
    if (idx >= 128 * 64) return;
    int n = idx >> 6, kp = idx & 63;
    int k0 = 2 * kp;
    const float* wb = (n < 64) ? (W2l + n) : (W2r + (n - 64));
    float a = wb[(size_t)k0 * 64];
    float c = wb[(size_t)(k0 + 1) * 64];
    uint32_t hi, lo;
    bf16_split2(a, c, hi, lo);
    g_w2hi[idx] = hi;
    g_w2lo[idx] = lo;
}

// ---------------- conv_x: x -> fp16 plane ----------------
__global__ void conv_x(const float* __restrict__ x) {
    int i = blockIdx.x * blockDim.x + threadIdx.x;
    if (i >= N_NODES * (CIN / 4)) return;
    float4 v = reinterpret_cast<const float4*>(x)[i];
    __half2* dst = reinterpret_cast<__half2*>(g_xh);
    dst[2 * i]     = __floats2half2_rn(v.x, v.y);
    dst[2 * i + 1] = __floats2half2_rn(v.z, v.w);
}

// ---------------- zero deg + init flag ----------------
__global__ void zero_deg() {
    int i = blockIdx.x * blockDim.x + threadIdx.x;
    if (i < N_NODES) g_degi[i] = 0;
    if (i == 0) g_is64 = 1;
}

// ---------------- detect edge_index dtype ----------------
__global__ void detect_kernel(const long long* __restrict__ ei, long long n) {
    long long i = (long long)blockIdx.x * blockDim.x + threadIdx.x;
    long long stride = (long long)gridDim.x * blockDim.x;
    for (; i < n; i += stride) {
        unsigned long long v = (unsigned long long)ei[i];
        if (v >= (unsigned long long)N_NODES) { g_is64 = 0; return; }
    }
}

// ---------------- decode edges + degree histogram ----------------
__global__ void decode_count(const void* __restrict__ ei_raw, int E) {
    int e = blockIdx.x * blockDim.x + threadIdx.x;
    if (e >= E) return;
    int src, dst;
    if (g_is64) {
        const long long* ei = (const long long*)ei_raw;
        src = (int)ei[e]; dst = (int)ei[(size_t)E + e];
    } else {
        const int* ei = (const int*)ei_raw;
        src = ei[e]; dst = ei[(size_t)E + e];
    }
    if ((unsigned)src >= N_NODES) src = 0;
    if ((unsigned)dst >= N_NODES) dst = 0;
    g_srcbuf[e] = src;
    g_dstbuf[e] = dst;
    atomicAdd(&g_degi[dst], 1);
}

// ---------------- scan phases ----------------
__global__ void block_sum_kernel() {
    int i = blockIdx.x * 256 + threadIdx.x;
    int v = (i < N_NODES) ? g_degi[i] : 0;
#pragma unroll
    for (int o = 16; o; o >>= 1) v += __shfl_down_sync(0xffffffffu, v, o);
    __shared__ int ws[8];
    if ((threadIdx.x & 31) == 0) ws[threadIdx.x >> 5] = v;
    __syncthreads();
    if (threadIdx.x < 8) {
        int s = ws[threadIdx.x];
#pragma unroll
        for (int o = 4; o; o >>= 1) s += __shfl_down_sync(0xffu, s, o);
        if (threadIdx.x == 0) g_bsum[blockIdx.x] = s;
    }
}

__global__ void scan_bsum_kernel() {
    __shared__ int sp[512];
    int tid = threadIdx.x;
    int v = (tid < SCAN_BLOCKS) ? g_bsum[tid] : 0;
    sp[tid] = v;
    __syncthreads();
    for (int off = 1; off < 512; off <<= 1) {
        int t = (tid >= off) ? sp[tid - off] : 0;
        __syncthreads();
        sp[tid] += t;
        __syncthreads();
    }
    if (tid < SCAN_BLOCKS) g_bsum[tid] = sp[tid] - v;
    if (tid == SCAN_BLOCKS - 1) g_row[N_NODES] = sp[tid];
}

__global__ void block_scan_kernel() {
    int i = blockIdx.x * 256 + threadIdx.x;
    int lane = threadIdx.x & 31, warp = threadIdx.x >> 5;
    int v = (i < N_NODES) ? g_degi[i] : 0;
    int s = v;
#pragma unroll
    for (int o = 1; o < 32; o <<= 1) {
        int t = __shfl_up_sync(0xffffffffu, s, o);
        if (lane >= o) s += t;
    }
    __shared__ int ws[8];
    if (lane == 31) ws[warp] = s;
    __syncthreads();
    if (threadIdx.x == 0) {
        int run = 0;
#pragma unroll
        for (int w = 0; w < 8; w++) { int t = ws[w]; ws[w] = run; run += t; }
    }
    __syncthreads();
    int excl = (s - v) + ws[warp] + g_bsum[blockIdx.x];
    if (i < N_NODES) { g_row[i] = excl; g_cursor[i] = excl; }
}

__global__ void scatter_kernel(int E) {
    int e = blockIdx.x * blockDim.x + threadIdx.x;
    if (e >= E) return;
    int dst = g_dstbuf[e];
    int pos = atomicAdd(&g_cursor[dst], 1);
    if (pos < MAXE) g_csr[pos] = g_srcbuf[e];
}

// ---------------- agg layer 1: mean of fp16 x, single 8B load per src/lane ----------------
__global__ void agg1_csr() {
    int w    = (blockIdx.x * blockDim.x + threadIdx.x) >> 5;
    int lane = threadIdx.x & 31;
    if (w >= N_NODES) return;
    const int beg = g_row[w], end = g_row[w + 1];
    float4 a0 = {0.f, 0.f, 0.f, 0.f}, a1 = {0.f, 0.f, 0.f, 0.f};
    int i = beg;
    for (; i + 1 < end; i += 2) {
        int s0 = g_csr[i], s1 = g_csr[i + 1];
        uint2 r0 = *(reinterpret_cast<const uint2*>(g_xh + (size_t)s0 * CIN) + lane);
        uint2 r1 = *(reinterpret_cast<const uint2*>(g_xh + (size_t)s1 * CIN) + lane);
        float2 f0 = __half22float2(*reinterpret_cast<__half2*>(&r0.x));
        float2 f1 = __half22float2(*reinterpret_cast<__half2*>(&r0.y));
        float2 e0 = __half22float2(*reinterpret_cast<__half2*>(&r1.x));
        float2 e1 = __half22float2(*reinterpret_cast<__half2*>(&r1.y));
        a0.x += f0.x; a0.y += f0.y; a0.z += f1.x; a0.w += f1.y;
        a1.x += e0.x; a1.y += e0.y; a1.z += e1.x; a1.w += e1.y;
    }
    if (i < end) {
        int s0 = g_csr[i];
        uint2 r0 = *(reinterpret_cast<const uint2*>(g_xh + (size_t)s0 * CIN) + lane);
        float2 f0 = __half22float2(*reinterpret_cast<__half2*>(&r0.x));
        float2 f1 = __half22float2(*reinterpret_cast<__half2*>(&r0.y));
        a0.x += f0.x; a0.y += f0.y; a0.z += f1.x; a0.w += f1.y;
    }
    float rd = 1.0f / fmaxf((float)(end - beg), 1.0f);
    float4 o = {(a0.x + a1.x) * rd, (a0.y + a1.y) * rd,
                (a0.z + a1.z) * rd, (a0.w + a1.w) * rd};
    *reinterpret_cast<float4*>(g_mean1 + (size_t)w * CIN + lane * 4) = o;
}

// ---------------- agg layer 2 + final: out = mean(t_fp16) + r ----------------
__global__ void agg2_final(float* __restrict__ out) {
    int w    = (blockIdx.x * blockDim.x + threadIdx.x) >> 5;
    int lane = threadIdx.x & 31;
    if (w >= N_NODES) return;
    const int beg = g_row[w], end = g_row[w + 1];
    const __half2* th = reinterpret_cast<const __half2*>(g_th);
    float2 a0 = {0.f, 0.f}, a1 = {0.f, 0.f};
    int i = beg;
    for (; i + 1 < end; i += 2) {
        int s0 = g_csr[i], s1 = g_csr[i + 1];
        float2 v0 = __half22float2(th[(size_t)s0 * 32 + lane]);
        float2 v1 = __half22float2(th[(size_t)s1 * 32 + lane]);
        a0.x += v0.x; a0.y += v0.y;
        a1.x += v1.x; a1.y += v1.y;
    }
    if (i < end) {
        int s0 = g_csr[i];
        float2 v0 = __half22float2(th[(size_t)s0 * 32 + lane]);
        a0.x += v0.x; a0.y += v0.y;
    }
    float rd = 1.0f / fmaxf((float)(end - beg), 1.0f);
    float2 r = *reinterpret_cast<const float2*>(g_r + (size_t)w * COUT + lane * 2);
    float2 o = {(a0.x + a1.x) * rd + r.x, (a0.y + a1.y) * rd + r.y};
    *reinterpret_cast<float2*>(out + (size_t)w * COUT + lane * 2) = o;
}

// ================= GEMM layer 1 (R12, unchanged) =================
__global__ void __launch_bounds__(256) gemm1_mma(const float* __restrict__ x,
                                                 const float* __restrict__ b1) {
    __shared__ uint32_t sAhi[64 * 20], sAlo[64 * 20];
    __shared__ uint32_t sBhi[128 * 20], sBlo[128 * 20];

    const int tid  = threadIdx.x;
    const int lane = tid & 31;
    const int wid  = tid >> 5;
    const int g    = lane >> 2;
    const int tig  = lane & 3;
    const int r0w  = (wid & 3) * 16;
    const int n0w  = (wid >> 2) * 64;
    const int block_m = blockIdx.x * 64;

    const int arow = tid >> 2;
    const int akq  = (tid & 3) * 8;
    const int anode = block_m + arow;
    const bool avalid = (anode < N_NODES);

    float acc[8][4];
#pragma unroll
    for (int nf = 0; nf < 8; nf++)
#pragma unroll
        for (int q = 0; q < 4; q++) acc[nf][q] = 0.f;

    for (int ch = 0; ch < 8; ch++) {
        const int kbase = ch * 32;
        {
            float v[8];
            if (avalid) {
                const float* src = (kbase < 128)
                    ? (g_mean1 + (size_t)anode * CIN + kbase + akq)
                    : (x + (size_t)anode * CIN + (kbase - 128) + akq);
                const float4* p = reinterpret_cast<const float4*>(src);
                float4 t0 = p[0], t1 = p[1];
                v[0]=t0.x; v[1]=t0.y; v[2]=t0.z; v[3]=t0.w;
                v[4]=t1.x; v[5]=t1.y; v[6]=t1.z; v[7]=t1.w;
            } else {
#pragma unroll
                for (int j = 0; j < 8; j++) v[j] = 0.f;
            }
            const int base = arow * 20 + (akq >> 1);
#pragma unroll
            for (int j = 0; j < 4; j++) {
                uint32_t hi, lo;
                bf16_split2(v[2*j], v[2*j+1], hi, lo);
                sAhi[base + j] = hi;
                sAlo[base + j] = lo;
            }
        }
        {
#pragma unroll
            for (int i = 0; i < 8; i++) {
                const int idx = tid + i * 256;
                const int n = idx >> 4, j = idx & 15;
                const int s = n * 20 + j;
                const int gsrc = n * 128 + ch * 16 + j;
                sBhi[s] = g_w1hi[gsrc];
                sBlo[s] = g_w1lo[gsrc];
            }
        }
        __syncthreads();

#pragma unroll
        for (int ks = 0; ks < 2; ks++) {
            const int kof = ks * 8;
            uint32_t ah[4], al[4];
            {
                const int i0 = (r0w + g) * 20 + kof + tig;
                const int i1 = (r0w + g + 8) * 20 + kof + tig;
                ah[0] = sAhi[i0];     ah[1] = sAhi[i1];
                ah[2] = sAhi[i0 + 4]; ah[3] = sAhi[i1 + 4];
                al[0] = sAlo[i0];     al[1] = sAlo[i1];
                al[2] = sAlo[i0 + 4]; al[3] = sAlo[i1 + 4];
            }
#pragma unroll
            for (int nf = 0; nf < 8; nf++) {
                const int nb = (n0w + nf * 8 + g) * 20 + kof + tig;
                uint32_t bh[2] = { sBhi[nb], sBhi[nb + 4] };
                uint32_t bl[2] = { sBlo[nb], sBlo[nb + 4] };
                mma_bf16(acc[nf], ah, bh);
                mma_bf16(acc[nf], ah, bl);
                mma_bf16(acc[nf], al, bh);
            }
        }
        __syncthreads();
    }

    const int row0 = block_m + r0w + g;
    const int row1 = row0 + 8;
#pragma unroll
    for (int nf = 0; nf < 8; nf++) {
        const int col = n0w + nf * 8 + 2 * tig;
        const float bb0 = b1[col], bb1 = b1[col + 1];
        if (row0 < N_NODES) {
            float2 o = {fmaxf(acc[nf][0] + bb0, 0.f), fmaxf(acc[nf][1] + bb1, 0.f)};
            *reinterpret_cast<float2*>(g_h + (size_t)row0 * CHID + col) = o;
        }
        if (row1 < N_NODES) {
            float2 o = {fmaxf(acc[nf][2] + bb0, 0.f), fmaxf(acc[nf][3] + bb1, 0.f)};
            *reinterpret_cast<float2*>(g_h + (size_t)row1 * CHID + col) = o;
        }
    }
}

// ================= GEMM layer 2 (R15, unchanged; t stored fp16) =================
__global__ void __launch_bounds__(256) gemm2_mma(const float* __restrict__ b2) {
    __shared__ uint32_t sAhi[64 * 20], sAlo[64 * 20];
    __shared__ uint32_t sBhi[128 * 20], sBlo[128 * 20];

    const int tid  = threadIdx.x;
    const int lane = tid & 31;
    const int wid  = tid >> 5;
    const int g    = lane >> 2;
    const int tig  = lane & 3;
    const int r0w  = (wid & 3) * 16;
    const int n0w  = (wid >> 2) * 64;
    const int block_m = blockIdx.x * 64;

    const int arow = tid >> 2;
    const int akq  = (tid & 3) * 8;
    const int anode = block_m + arow;
    const bool avalid = (anode < N_NODES);

    float acc[8][4];
#pragma unroll
    for (int nf = 0; nf < 8; nf++)
#pragma unroll
        for (int q = 0; q < 4; q++) acc[nf][q] = 0.f;

    for (int ch = 0; ch < 4; ch++) {
        const int kbase = ch * 32;
        {
            float v[8];
            if (avalid) {
                const float4* p = reinterpret_cast<const float4*>(
                    g_h + (size_t)anode * CHID + kbase + akq);
                float4 t0 = p[0], t1 = p[1];
                v[0]=t0.x; v[1]=t0.y; v[2]=t0.z; v[3]=t0.w;
                v[4]=t1.x; v[5]=t1.y; v[6]=t1.z; v[7]=t1.w;
            } else {
#pragma unroll
                for (int j = 0; j < 8; j++) v[j] = 0.f;
            }
            const int base = arow * 20 + (akq >> 1);
#pragma unroll
            for (int j = 0; j < 4; j++) {
                uint32_t hi, lo;
                bf16_split2(v[2*j], v[2*j+1], hi, lo);
                sAhi[base + j] = hi;
                sAlo[base + j] = lo;
            }
        }
        {
#pragma unroll
            for (int i = 0; i < 8; i++) {
                const int idx = tid + i * 256;
                const int n = idx >> 4, j = idx & 15;
                const int s = n * 20 + j;
                const int gsrc = n * 64 + ch * 16 + j;
                sBhi[s] = g_w2hi[gsrc];
                sBlo[s] = g_w2lo[gsrc];
            }
        }
        __syncthreads();

#pragma unroll
        for (int ks = 0; ks < 2; ks++) {
            const int kof = ks * 8;
            uint32_t ah[4], al[4];
            {
                const int i0 = (r0w + g) * 20 + kof + tig;
                const int i1 = (r0w + g + 8) * 20 + kof + tig;
                ah[0] = sAhi[i0];     ah[1] = sAhi[i1];
                ah[2] = sAhi[i0 + 4]; ah[3] = sAhi[i1 + 4];
                al[0] = sAlo[i0];     al[1] = sAlo[i1];
                al[2] = sAlo[i0 + 4]; al[3] = sAlo[i1 + 4];
            }
#pragma unroll
            for (int nf = 0; nf < 8; nf++) {
                const int nb = (n0w + nf * 8 + g) * 20 + kof + tig;
                uint32_t bh[2] = { sBhi[nb], sBhi[nb + 4] };
                uint32_t bl[2] = { sBlo[nb], sBlo[nb + 4] };
                mma_bf16(acc[nf], ah, bh);
                mma_bf16(acc[nf], ah, bl);
                mma_bf16(acc[nf], al, bh);
            }
        }
        __syncthreads();
    }

    const int row0 = block_m + r0w + g;
    const int row1 = row0 + 8;
#pragma unroll
    for (int nf = 0; nf < 8; nf++) {
        const int col = n0w + nf * 8 + 2 * tig;
        if (col < 64) {
            if (row0 < N_NODES) {
                __half2 o = __floats2half2_rn(acc[nf][0], acc[nf][1]);
                *reinterpret_cast<__half2*>(g_th + (size_t)row0 * COUT + col) = o;
            }
            if (row1 < N_NODES) {
                __half2 o = __floats2half2_rn(acc[nf][2], acc[nf][3]);
                *reinterpret_cast<__half2*>(g_th + (size_t)row1 * COUT + col) = o;
            }
        } else {
            const int cc = col - 64;
            const float bb0 = b2[cc], bb1 = b2[cc + 1];
            if (row0 < N_NODES) {
                float2 o = {acc[nf][0] + bb0, acc[nf][1] + bb1};
                *reinterpret_cast<float2*>(g_r + (size_t)row0 * COUT + cc) = o;
            }
            if (row1 < N_NODES) {
                float2 o = {acc[nf][2] + bb0, acc[nf][3] + bb1};
                *reinterpret_cast<float2*>(g_r + (size_t)row1 * COUT + cc) = o;
            }
        }
    }
}

// ---------------- launch ----------------
extern "C" void kernel_launch(void* const* d_in, const int* in_sizes, int n_in,
                              void* d_out, int out_size) {
    const float* x   = (const float*)d_in[0];
    const void*  ei  = d_in[1];
    const float* W1l = (const float*)d_in[2];
    const float* W1r = (const float*)d_in[3];
    const float* b1  = (const float*)d_in[4];
    const float* W2l = (const float*)d_in[5];
    const float* W2r = (const float*)d_in[6];
    const float* b2  = (const float*)d_in[7];
    float* out = (float*)d_out;

    const int E = in_sizes[1] / 2;

    // lazily created once (outside any capture: first call is the correctness run)
    static cudaStream_t sB = nullptr;
    static cudaEvent_t evF = nullptr, evJ = nullptr;
    if (sB == nullptr) {
        cudaStreamCreateWithFlags(&sB, cudaStreamNonBlocking);
        cudaEventCreateWithFlags(&evF, cudaEventDisableTiming);
        cudaEventCreateWithFlags(&evJ, cudaEventDisableTiming);
    }

    // ---- fork: conv_x (DRAM-bound) overlaps the L2-bound CSR build ----
    cudaEventRecord(evF, 0);
    cudaStreamWaitEvent(sB, evF, 0);
    {
        int blocks = (N_NODES * (CIN / 4) + 255) / 256;
        conv_x<<<blocks, 256, 0, sB>>>(x);
    }
    cudaEventRecord(evJ, sB);

    // ---- main stream: prep + CSR build ----
    {
        int blocks = (N_NODES + 255) / 256;
        zero_deg<<<blocks, 256>>>();
        prep_w1<<<64, 256>>>(W1l, W1r);
        prep_w2<<<32, 256>>>(W2l, W2r);
    }
    {
        long long n64_safe = (long long)E / 2;
        detect_kernel<<<1024, 256>>>((const long long*)ei, n64_safe);
    }
    {
        int blocks = (E + 255) / 256;
        decode_count<<<blocks, 256>>>(ei, E);
        block_sum_kernel<<<SCAN_BLOCKS, 256>>>();
        scan_bsum_kernel<<<1, 512>>>();
        block_scan_kernel<<<SCAN_BLOCKS, 256>>>();
        scatter_kernel<<<blocks, 256>>>(E);
    }

    // ---- join conv_x, then aggregation + GEMMs ----
    cudaStreamWaitEvent(0, evJ, 0);
    {
        long long threads = (long long)N_NODES * 32;
        int blocks = (int)((threads + 255) / 256);
        agg1_csr<<<blocks, 256>>>();
    }
    {
        int blocks = (N_NODES + 63) / 64;
        gemm1_mma<<<blocks, 256>>>(x, b1);
        gemm2_mma<<<blocks, 256>>>(b2);
    }
    {
        long long threads = (long long)N_NODES * 32;
        int blocks = (int)((threads + 255) / 256);
        agg2_final<<<blocks, 256>>>(out);
    }
}

// round 17
// speedup vs baseline: 1.3793x; 1.3239x over previous
#include <cuda_runtime.h>
#include <cuda_fp16.h>
#include <cstdint>

#define N_NODES 100000
#define CIN 128
#define CHID 128
#define COUT 64
#define MAXE 1600000
#define SCAN_BLOCKS ((N_NODES + 255) / 256)

// ---------------- scratch ----------------
__device__ __align__(16) float  g_mean1[(size_t)N_NODES * CIN];
__device__ __align__(16) float  g_h    [(size_t)N_NODES * CHID];
__device__ __align__(16) __half g_th   [(size_t)N_NODES * COUT];   // t = h @ W2l (fp16)
__device__ __align__(16) float  g_r    [(size_t)N_NODES * COUT];
__device__ __align__(16) __half g_xh   [(size_t)N_NODES * CIN];    // fp16 copy of x
__device__ int g_degi  [N_NODES];
__device__ int g_row   [N_NODES + 1];
__device__ int g_cursor[N_NODES];
__device__ int g_srcbuf[MAXE];
__device__ int g_dstbuf[MAXE];
__device__ int g_csr   [MAXE];
__device__ int g_bsum  [512];
__device__ int g_is64;
// pre-converted fp16 weights, transposed [n][kpair] u32 (half2)
__device__ __align__(16) uint32_t g_w1h[128 * 128];
__device__ __align__(16) uint32_t g_w2h[128 * 64];

// mma.sync m16n8k16 row.col f32.f16.f16.f32, D += A*B
__device__ __forceinline__ void mma_f16(float* d, const uint32_t* a,
                                        const uint32_t* b) {
    asm volatile(
        "mma.sync.aligned.m16n8k16.row.col.f32.f16.f16.f32 "
        "{%0,%1,%2,%3}, {%4,%5,%6,%7}, {%8,%9}, {%0,%1,%2,%3};"
        : "+f"(d[0]), "+f"(d[1]), "+f"(d[2]), "+f"(d[3])
        : "r"(a[0]), "r"(a[1]), "r"(a[2]), "r"(a[3]), "r"(b[0]), "r"(b[1]));
}

__device__ __forceinline__ uint32_t packh2(float f0, float f1) {
    __half2 h = __floats2half2_rn(f0, f1);
    return *reinterpret_cast<uint32_t*>(&h);
}

// ---------------- prep: W1/W2 -> fp16, transposed [n][kpair] ----------------
__global__ void prep_w1(const float* __restrict__ W1l,
                        const float* __restrict__ W1r) {
    int idx = blockIdx.x * blockDim.x + threadIdx.x;
    if (idx >= 128 * 128) return;
    int n = idx >> 7, kp = idx & 127;
    int k0 = 2 * kp;
    float a = (k0 < 128) ? W1l[(size_t)k0 * 128 + n] : W1r[(size_t)(k0 - 128) * 128 + n];
    float c = (k0 + 1 < 128) ? W1l[(size_t)(k0 + 1) * 128 + n]
                             : W1r[(size_t)(k0 + 1 - 128) * 128 + n];
    g_w1h[idx] = packh2(a, c);
}

__global__ void prep_w2(const float* __restrict__ W2l,
                        const float* __restrict__ W2r) {
    int idx = blockIdx.x * blockDim.x + threadIdx.x;
    if (idx >= 128 * 64) return;
    int n = idx >> 6, kp = idx & 63;
    int k0 = 2 * kp;
    const float* wb = (n < 64) ? (W2l + n) : (W2r + (n - 64));
    g_w2h[idx] = packh2(wb[(size_t)k0 * 64], wb[(size_t)(k0 + 1) * 64]);
}

// ---------------- conv_x: x -> fp16 plane ----------------
__global__ void conv_x(const float* __restrict__ x) {
    int i = blockIdx.x * blockDim.x + threadIdx.x;
    if (i >= N_NODES * (CIN / 4)) return;
    float4 v = reinterpret_cast<const float4*>(x)[i];
    __half2* dst = reinterpret_cast<__half2*>(g_xh);
    dst[2 * i]     = __floats2half2_rn(v.x, v.y);
    dst[2 * i + 1] = __floats2half2_rn(v.z, v.w);
}

// ---------------- zero deg + init flag ----------------
__global__ void zero_deg() {
    int i = blockIdx.x * blockDim.x + threadIdx.x;
    if (i < N_NODES) g_degi[i] = 0;
    if (i == 0) g_is64 = 1;
}

// ---------------- detect edge_index dtype ----------------
__global__ void detect_kernel(const long long* __restrict__ ei, long long n) {
    long long i = (long long)blockIdx.x * blockDim.x + threadIdx.x;
    long long stride = (long long)gridDim.x * blockDim.x;
    for (; i < n; i += stride) {
        unsigned long long v = (unsigned long long)ei[i];
        if (v >= (unsigned long long)N_NODES) { g_is64 = 0; return; }
    }
}

// ---------------- decode edges + degree histogram ----------------
__global__ void decode_count(const void* __restrict__ ei_raw, int E) {
    int e = blockIdx.x * blockDim.x + threadIdx.x;
    if (e >= E) return;
    int src, dst;
    if (g_is64) {
        const long long* ei = (const long long*)ei_raw;
        src = (int)ei[e]; dst = (int)ei[(size_t)E + e];
    } else {
        const int* ei = (const int*)ei_raw;
        src = ei[e]; dst = ei[(size_t)E + e];
    }
    if ((unsigned)src >= N_NODES) src = 0;
    if ((unsigned)dst >= N_NODES) dst = 0;
    g_srcbuf[e] = src;
    g_dstbuf[e] = dst;
    atomicAdd(&g_degi[dst], 1);
}

// ---------------- scan phases ----------------
__global__ void block_sum_kernel() {
    int i = blockIdx.x * 256 + threadIdx.x;
    int v = (i < N_NODES) ? g_degi[i] : 0;
#pragma unroll
    for (int o = 16; o; o >>= 1) v += __shfl_down_sync(0xffffffffu, v, o);
    __shared__ int ws[8];
    if ((threadIdx.x & 31) == 0) ws[threadIdx.x >> 5] = v;
    __syncthreads();
    if (threadIdx.x < 8) {
        int s = ws[threadIdx.x];
#pragma unroll
        for (int o = 4; o; o >>= 1) s += __shfl_down_sync(0xffu, s, o);
        if (threadIdx.x == 0) g_bsum[blockIdx.x] = s;
    }
}

__global__ void scan_bsum_kernel() {
    __shared__ int sp[512];
    int tid = threadIdx.x;
    int v = (tid < SCAN_BLOCKS) ? g_bsum[tid] : 0;
    sp[tid] = v;
    __syncthreads();
    for (int off = 1; off < 512; off <<= 1) {
        int t = (tid >= off) ? sp[tid - off] : 0;
        __syncthreads();
        sp[tid] += t;
        __syncthreads();
    }
    if (tid < SCAN_BLOCKS) g_bsum[tid] = sp[tid] - v;
    if (tid == SCAN_BLOCKS - 1) g_row[N_NODES] = sp[tid];
}

__global__ void block_scan_kernel() {
    int i = blockIdx.x * 256 + threadIdx.x;
    int lane = threadIdx.x & 31, warp = threadIdx.x >> 5;
    int v = (i < N_NODES) ? g_degi[i] : 0;
    int s = v;
#pragma unroll
    for (int o = 1; o < 32; o <<= 1) {
        int t = __shfl_up_sync(0xffffffffu, s, o);
        if (lane >= o) s += t;
    }
    __shared__ int ws[8];
    if (lane == 31) ws[warp] = s;
    __syncthreads();
    if (threadIdx.x == 0) {
        int run = 0;
#pragma unroll
        for (int w = 0; w < 8; w++) { int t = ws[w]; ws[w] = run; run += t; }
    }
    __syncthreads();
    int excl = (s - v) + ws[warp] + g_bsum[blockIdx.x];
    if (i < N_NODES) { g_row[i] = excl; g_cursor[i] = excl; }
}

__global__ void scatter_kernel(int E) {
    int e = blockIdx.x * blockDim.x + threadIdx.x;
    if (e >= E) return;
    int dst = g_dstbuf[e];
    int pos = atomicAdd(&g_cursor[dst], 1);
    if (pos < MAXE) g_csr[pos] = g_srcbuf[e];
}

// ---------------- agg layer 1: mean of fp16 x ----------------
__global__ void agg1_csr() {
    int w    = (blockIdx.x * blockDim.x + threadIdx.x) >> 5;
    int lane = threadIdx.x & 31;
    if (w >= N_NODES) return;
    const int beg = g_row[w], end = g_row[w + 1];
    float4 a0 = {0.f, 0.f, 0.f, 0.f}, a1 = {0.f, 0.f, 0.f, 0.f};
    int i = beg;
    for (; i + 1 < end; i += 2) {
        int s0 = g_csr[i], s1 = g_csr[i + 1];
        uint2 r0 = *(reinterpret_cast<const uint2*>(g_xh + (size_t)s0 * CIN) + lane);
        uint2 r1 = *(reinterpret_cast<const uint2*>(g_xh + (size_t)s1 * CIN) + lane);
        float2 f0 = __half22float2(*reinterpret_cast<__half2*>(&r0.x));
        float2 f1 = __half22float2(*reinterpret_cast<__half2*>(&r0.y));
        float2 e0 = __half22float2(*reinterpret_cast<__half2*>(&r1.x));
        float2 e1 = __half22float2(*reinterpret_cast<__half2*>(&r1.y));
        a0.x += f0.x; a0.y += f0.y; a0.z += f1.x; a0.w += f1.y;
        a1.x += e0.x; a1.y += e0.y; a1.z += e1.x; a1.w += e1.y;
    }
    if (i < end) {
        int s0 = g_csr[i];
        uint2 r0 = *(reinterpret_cast<const uint2*>(g_xh + (size_t)s0 * CIN) + lane);
        float2 f0 = __half22float2(*reinterpret_cast<__half2*>(&r0.x));
        float2 f1 = __half22float2(*reinterpret_cast<__half2*>(&r0.y));
        a0.x += f0.x; a0.y += f0.y; a0.z += f1.x; a0.w += f1.y;
    }
    float rd = 1.0f / fmaxf((float)(end - beg), 1.0f);
    float4 o = {(a0.x + a1.x) * rd, (a0.y + a1.y) * rd,
                (a0.z + a1.z) * rd, (a0.w + a1.w) * rd};
    *reinterpret_cast<float4*>(g_mean1 + (size_t)w * CIN + lane * 4) = o;
}

// ---------------- agg layer 2 + final ----------------
__global__ void agg2_final(float* __restrict__ out) {
    int w    = (blockIdx.x * blockDim.x + threadIdx.x) >> 5;
    int lane = threadIdx.x & 31;
    if (w >= N_NODES) return;
    const int beg = g_row[w], end = g_row[w + 1];
    const __half2* th = reinterpret_cast<const __half2*>(g_th);
    float2 a0 = {0.f, 0.f}, a1 = {0.f, 0.f};
    int i = beg;
    for (; i + 1 < end; i += 2) {
        int s0 = g_csr[i], s1 = g_csr[i + 1];
        float2 v0 = __half22float2(th[(size_t)s0 * 32 + lane]);
        float2 v1 = __half22float2(th[(size_t)s1 * 32 + lane]);
        a0.x += v0.x; a0.y += v0.y;
        a1.x += v1.x; a1.y += v1.y;
    }
    if (i < end) {
        int s0 = g_csr[i];
        float2 v0 = __half22float2(th[(size_t)s0 * 32 + lane]);
        a0.x += v0.x; a0.y += v0.y;
    }
    float rd = 1.0f / fmaxf((float)(end - beg), 1.0f);
    float2 r = *reinterpret_cast<const float2*>(g_r + (size_t)w * COUT + lane * 2);
    float2 o = {(a0.x + a1.x) * rd + r.x, (a0.y + a1.y) * rd + r.y};
    *reinterpret_cast<float2*>(out + (size_t)w * COUT + lane * 2) = o;
}

// ================= GEMM layer 1: single fp16 MMA =================
// h = relu([mean1 | x] @ [W1l ; W1r] + b1)
__global__ void __launch_bounds__(256) gemm1_mma(const float* __restrict__ b1) {
    __shared__ uint32_t sA[64 * 20];
    __shared__ uint32_t sB[128 * 20];

    const int tid  = threadIdx.x;
    const int lane = tid & 31;
    const int wid  = tid >> 5;
    const int g    = lane >> 2;
    const int tig  = lane & 3;
    const int r0w  = (wid & 3) * 16;
    const int n0w  = (wid >> 2) * 64;
    const int block_m = blockIdx.x * 64;

    const int arow = tid >> 2;
    const int akq  = (tid & 3) * 8;
    const int anode = block_m + arow;
    const bool avalid = (anode < N_NODES);

    float acc[8][4];
#pragma unroll
    for (int nf = 0; nf < 8; nf++)
#pragma unroll
        for (int q = 0; q < 4; q++) acc[nf][q] = 0.f;

    for (int ch = 0; ch < 8; ch++) {
        const int kbase = ch * 32;

        // ---- A chunk ----
        {
            const int base = arow * 20 + (akq >> 1);
            if (avalid) {
                if (kbase < 128) {
                    // mean1 (fp32) -> fp16
                    const float4* p = reinterpret_cast<const float4*>(
                        g_mean1 + (size_t)anode * CIN + kbase + akq);
                    float4 t0 = p[0], t1 = p[1];
                    sA[base + 0] = packh2(t0.x, t0.y);
                    sA[base + 1] = packh2(t0.z, t0.w);
                    sA[base + 2] = packh2(t1.x, t1.y);
                    sA[base + 3] = packh2(t1.z, t1.w);
                } else {
                    // x already fp16 in g_xh: copy 8 halves = uint4
                    uint4 r = *reinterpret_cast<const uint4*>(
                        g_xh + (size_t)anode * CIN + (kbase - 128) + akq);
                    sA[base + 0] = r.x;
                    sA[base + 1] = r.y;
                    sA[base + 2] = r.z;
                    sA[base + 3] = r.w;
                }
            } else {
                sA[base + 0] = 0; sA[base + 1] = 0;
                sA[base + 2] = 0; sA[base + 3] = 0;
            }
        }
        // ---- W chunk ----
        {
#pragma unroll
            for (int i = 0; i < 8; i++) {
                const int idx = tid + i * 256;
                const int n = idx >> 4, j = idx & 15;
                sB[n * 20 + j] = g_w1h[n * 128 + ch * 16 + j];
            }
        }
        __syncthreads();

#pragma unroll
        for (int ks = 0; ks < 2; ks++) {
            const int kof = ks * 8;
            uint32_t a[4];
            {
                const int i0 = (r0w + g) * 20 + kof + tig;
                const int i1 = (r0w + g + 8) * 20 + kof + tig;
                a[0] = sA[i0];     a[1] = sA[i1];
                a[2] = sA[i0 + 4]; a[3] = sA[i1 + 4];
            }
#pragma unroll
            for (int nf = 0; nf < 8; nf++) {
                const int nb = (n0w + nf * 8 + g) * 20 + kof + tig;
                uint32_t b[2] = { sB[nb], sB[nb + 4] };
                mma_f16(acc[nf], a, b);
            }
        }
        __syncthreads();
    }

    const int row0 = block_m + r0w + g;
    const int row1 = row0 + 8;
#pragma unroll
    for (int nf = 0; nf < 8; nf++) {
        const int col = n0w + nf * 8 + 2 * tig;
        const float bb0 = b1[col], bb1 = b1[col + 1];
        if (row0 < N_NODES) {
            float2 o = {fmaxf(acc[nf][0] + bb0, 0.f), fmaxf(acc[nf][1] + bb1, 0.f)};
            *reinterpret_cast<float2*>(g_h + (size_t)row0 * CHID + col) = o;
        }
        if (row1 < N_NODES) {
            float2 o = {fmaxf(acc[nf][2] + bb0, 0.f), fmaxf(acc[nf][3] + bb1, 0.f)};
            *reinterpret_cast<float2*>(g_h + (size_t)row1 * CHID + col) = o;
        }
    }
}

// ================= GEMM layer 2: single fp16 MMA =================
// [t | r] = h @ [W2l | W2r] (+ [0 | b2]); t stored fp16
__global__ void __launch_bounds__(256) gemm2_mma(const float* __restrict__ b2) {
    __shared__ uint32_t sA[64 * 20];
    __shared__ uint32_t sB[128 * 20];

    const int tid  = threadIdx.x;
    const int lane = tid & 31;
    const int wid  = tid >> 5;
    const int g    = lane >> 2;
    const int tig  = lane & 3;
    const int r0w  = (wid & 3) * 16;
    const int n0w  = (wid >> 2) * 64;
    const int block_m = blockIdx.x * 64;

    const int arow = tid >> 2;
    const int akq  = (tid & 3) * 8;
    const int anode = block_m + arow;
    const bool avalid = (anode < N_NODES);

    float acc[8][4];
#pragma unroll
    for (int nf = 0; nf < 8; nf++)
#pragma unroll
        for (int q = 0; q < 4; q++) acc[nf][q] = 0.f;

    for (int ch = 0; ch < 4; ch++) {
        const int kbase = ch * 32;
        {
            const int base = arow * 20 + (akq >> 1);
            if (avalid) {
                const float4* p = reinterpret_cast<const float4*>(
                    g_h + (size_t)anode * CHID + kbase + akq);
                float4 t0 = p[0], t1 = p[1];
                sA[base + 0] = packh2(t0.x, t0.y);
                sA[base + 1] = packh2(t0.z, t0.w);
                sA[base + 2] = packh2(t1.x, t1.y);
                sA[base + 3] = packh2(t1.z, t1.w);
            } else {
                sA[base + 0] = 0; sA[base + 1] = 0;
                sA[base + 2] = 0; sA[base + 3] = 0;
            }
        }
        {
#pragma unroll
            for (int i = 0; i < 8; i++) {
                const int idx = tid + i * 256;
                const int n = idx >> 4, j = idx & 15;
                sB[n * 20 + j] = g_w2h[n * 64 + ch * 16 + j];
            }
        }
        __syncthreads();

#pragma unroll
        for (int ks = 0; ks < 2; ks++) {
            const int kof = ks * 8;
            uint32_t a[4];
            {
                const int i0 = (r0w + g) * 20 + kof + tig;
                const int i1 = (r0w + g + 8) * 20 + kof + tig;
                a[0] = sA[i0];     a[1] = sA[i1];
                a[2] = sA[i0 + 4]; a[3] = sA[i1 + 4];
            }
#pragma unroll
            for (int nf = 0; nf < 8; nf++) {
                const int nb = (n0w + nf * 8 + g) * 20 + kof + tig;
                uint32_t b[2] = { sB[nb], sB[nb + 4] };
                mma_f16(acc[nf], a, b);
            }
        }
        __syncthreads();
    }

    const int row0 = block_m + r0w + g;
    const int row1 = row0 + 8;
#pragma unroll
    for (int nf = 0; nf < 8; nf++) {
        const int col = n0w + nf * 8 + 2 * tig;
        if (col < 64) {
            if (row0 < N_NODES) {
                __half2 o = __floats2half2_rn(acc[nf][0], acc[nf][1]);
                *reinterpret_cast<__half2*>(g_th + (size_t)row0 * COUT + col) = o;
            }
            if (row1 < N_NODES) {
                __half2 o = __floats2half2_rn(acc[nf][2], acc[nf][3]);
                *reinterpret_cast<__half2*>(g_th + (size_t)row1 * COUT + col) = o;
            }
        } else {
            const int cc = col - 64;
            const float bb0 = b2[cc], bb1 = b2[cc + 1];
            if (row0 < N_NODES) {
                float2 o = {acc[nf][0] + bb0, acc[nf][1] + bb1};
                *reinterpret_cast<float2*>(g_r + (size_t)row0 * COUT + cc) = o;
            }
            if (row1 < N_NODES) {
                float2 o = {acc[nf][2] + bb0, acc[nf][3] + bb1};
                *reinterpret_cast<float2*>(g_r + (size_t)row1 * COUT + cc) = o;
            }
        }
    }
}

// ---------------- launch ----------------
extern "C" void kernel_launch(void* const* d_in, const int* in_sizes, int n_in,
                              void* d_out, int out_size) {
    const float* x   = (const float*)d_in[0];
    const void*  ei  = d_in[1];
    const float* W1l = (const float*)d_in[2];
    const float* W1r = (const float*)d_in[3];
    const float* b1  = (const float*)d_in[4];
    const float* W2l = (const float*)d_in[5];
    const float* W2r = (const float*)d_in[6];
    const float* b2  = (const float*)d_in[7];
    float* out = (float*)d_out;

    const int E = in_sizes[1] / 2;

    static cudaStream_t sB = nullptr;
    static cudaEvent_t evF = nullptr, evJ = nullptr;
    if (sB == nullptr) {
        cudaStreamCreateWithFlags(&sB, cudaStreamNonBlocking);
        cudaEventCreateWithFlags(&evF, cudaEventDisableTiming);
        cudaEventCreateWithFlags(&evJ, cudaEventDisableTiming);
    }

    // ---- fork: conv_x (DRAM-bound) overlaps the L2-bound CSR build ----
    cudaEventRecord(evF, 0);
    cudaStreamWaitEvent(sB, evF, 0);
    {
        int blocks = (N_NODES * (CIN / 4) + 255) / 256;
        conv_x<<<blocks, 256, 0, sB>>>(x);
    }
    cudaEventRecord(evJ, sB);

    // ---- main stream: prep + CSR build ----
    {
        int blocks = (N_NODES + 255) / 256;
        zero_deg<<<blocks, 256>>>();
        prep_w1<<<64, 256>>>(W1l, W1r);
        prep_w2<<<32, 256>>>(W2l, W2r);
    }
    {
        long long n64_safe = (long long)E / 2;
        detect_kernel<<<1024, 256>>>((const long long*)ei, n64_safe);
    }
    {
        int blocks = (E + 255) / 256;
        decode_count<<<blocks, 256>>>(ei, E);
        block_sum_kernel<<<SCAN_BLOCKS, 256>>>();
        scan_bsum_kernel<<<1, 512>>>();
        block_scan_kernel<<<SCAN_BLOCKS, 256>>>();
        scatter_kernel<<<blocks, 256>>>(E);
    }

    // ---- join conv_x, then aggregation + GEMMs ----
    cudaStreamWaitEvent(0, evJ, 0);
    {
        long long threads = (long long)N_NODES * 32;
        int blocks = (int)((threads + 255) / 256);
        agg1_csr<<<blocks, 256>>>();
    }
    {
        int blocks = (N_NODES + 63) / 64;
        gemm1_mma<<<blocks, 256>>>(b1);
        gemm2_mma<<<blocks, 256>>>(b2);
    }
    {
        long long threads = (long long)N_NODES * 32;
        int blocks = (int)((threads + 255) / 256);
        agg2_final<<<blocks, 256>>>(out);
    }
}